// round 9
// baseline (speedup 1.0000x reference)
#include <cuda_runtime.h>
#include <math.h>

#define LVL 4
#define BAT 128
#define INW 512
#define CTXW 512
#define STW 512
#define RW 256
#define CW 256
#define DW 1536
#define KC 32
#define NCHUNK (DW/KC)                /* 48 */
#define H_SIZE (LVL*BAT*STW)          /* 262144 */
#define H_SIZE4 (H_SIZE/4)            /* 65536 */
#define M_LVL_STRIDE (BAT*RW*CW)      /* 8388608 */

// scratch (allocation-free rule: __device__ globals)
__device__ __align__(16) float g_gate[3][LVL][BAT][STW];  // phi/alpha/beta raw (3 MB)
__device__ __align__(16) float g_uv[2][LVL][BAT][RW];     // u,v raw (1 MB)

__device__ __forceinline__ float sigmoidf_(float x) { return 1.0f / (1.0f + __expf(-x)); }

__device__ __forceinline__ unsigned f2tf(float x) {
    unsigned r;
    asm("cvt.rna.tf32.f32 %0, %1;" : "=r"(r) : "f"(x));
    return r;
}

__device__ __forceinline__ void mma_tf32(float* d, unsigned a0, unsigned a1,
                                         unsigned a2, unsigned a3,
                                         unsigned b0, unsigned b1)
{
    asm volatile(
        "mma.sync.aligned.m16n8k8.row.col.f32.tf32.tf32.f32 "
        "{%0,%1,%2,%3}, {%4,%5,%6,%7}, {%8,%9}, {%0,%1,%2,%3};\n"
        : "+f"(d[0]), "+f"(d[1]), "+f"(d[2]), "+f"(d[3])
        : "r"(a0), "r"(a1), "r"(a2), "r"(a3), "r"(b0), "r"(b1));
}

__device__ __forceinline__ void cp16(void* dst, const void* src) {
    unsigned ds = (unsigned)__cvta_generic_to_shared(dst);
    asm volatile("cp.async.ca.shared.global [%0], [%1], 16;" :: "r"(ds), "l"(src));
}
__device__ __forceinline__ void cp_commit() { asm volatile("cp.async.commit_group;"); }
template<int N> __device__ __forceinline__ void cp_wait() {
    asm volatile("cp.async.wait_group %0;" :: "n"(N));
}

// ---------------------------------------------------------------------------
// Gate GEMM: g_gate[gate][l][b][o] = gi[l,b,:] . W[l,o,:] + bias
// gi = x|c|h[l].  Block tile M=64(batch) x N=64(out), 128 threads (4 warps,
// 2x2), warp tile 32x32.  Double-buffered cp.async: issue next-stage group
// FIRST, then cp_wait<1> drains the current stage while the next stays in
// flight across the MMA body (issue-after-wait was the R6 correctness bug —
// wait<1> with only 1 pending group returns without waiting).
// Stride-36 smem rows -> conflict-free fragment reads (bank=(4g+tg)%32).
// grid: (otile=8, mtile=2, z=l*3+gate=12) = 192 blocks.
// ---------------------------------------------------------------------------
__global__ __launch_bounds__(128)
void gate_gemm(const float* __restrict__ x, const float* __restrict__ c,
               const float* __restrict__ h,
               const float* __restrict__ phi_w, const float* __restrict__ alpha_w,
               const float* __restrict__ beta_w,
               const float* __restrict__ phi_b, const float* __restrict__ alpha_b,
               const float* __restrict__ beta_b)
{
    __shared__ float As[2][64][36];
    __shared__ float Bs[2][64][36];

    const int zz = blockIdx.z;
    const int l = zz / 3, gate = zz % 3;
    const int mtile = blockIdx.y;
    const int otile = blockIdx.x;
    const int t = threadIdx.x;
    const int w = t >> 5, lane = t & 31;
    const int wm = w >> 1, wn = w & 1;     // 2x2 warp grid
    const int g = lane >> 2, tg = lane & 3;

    const float* W    = (gate == 0 ? phi_w : gate == 1 ? alpha_w : beta_w) + (size_t)l * STW * DW;
    const float* bias = (gate == 0 ? phi_b : gate == 1 ? alpha_b : beta_b) + l * STW;

    float acc[2][4][4];
    #pragma unroll
    for (int mi = 0; mi < 2; mi++)
        #pragma unroll
        for (int ni = 0; ni < 4; ni++)
            #pragma unroll
            for (int r = 0; r < 4; r++) acc[mi][ni][r] = 0.0f;

    // one KC=32 chunk into stage s: A 64x32, B 64x32 (4 float4 each / thread)
    auto load_chunk = [&](int kt, int s) {
        #pragma unroll
        for (int i = 0; i < 4; i++) {
            const int idx = i * 128 + t;
            const int row = idx >> 3, ch = idx & 7;
            const int k = kt + ch * 4;
            const int b = mtile * 64 + row;
            const float* src;
            if (k < INW)              src = x + (size_t)b * INW + k;
            else if (k < INW + CTXW)  src = c + (size_t)b * CTXW + (k - INW);
            else                      src = h + ((size_t)l * BAT + b) * STW + (k - INW - CTXW);
            cp16(&As[s][row][ch * 4], src);
        }
        #pragma unroll
        for (int i = 0; i < 4; i++) {
            const int idx = i * 128 + t;
            const int row = idx >> 3, ch = idx & 7;
            cp16(&Bs[s][row][ch * 4], W + (size_t)(otile * 64 + row) * DW + kt + ch * 4);
        }
        cp_commit();
    };

    load_chunk(0, 0);
    for (int it = 0; it < NCHUNK; ++it) {
        const int s = it & 1;
        // Writing stage s^1 is safe: all reads of it finished at the
        // trailing barrier of the previous iteration.
        if (it + 1 < NCHUNK) { load_chunk((it + 1) * KC, s ^ 1); cp_wait<1>(); }
        else                 { cp_wait<0>(); }
        __syncthreads();

        #pragma unroll
        for (int ks = 0; ks < 4; ks++) {
            const int k0 = ks * 8;
            unsigned a[2][4];
            #pragma unroll
            for (int mi = 0; mi < 2; mi++) {
                const int r0 = wm * 32 + mi * 16;
                a[mi][0] = f2tf(As[s][r0 + g][k0 + tg]);
                a[mi][1] = f2tf(As[s][r0 + g + 8][k0 + tg]);
                a[mi][2] = f2tf(As[s][r0 + g][k0 + tg + 4]);
                a[mi][3] = f2tf(As[s][r0 + g + 8][k0 + tg + 4]);
            }
            unsigned bb[4][2];
            #pragma unroll
            for (int ni = 0; ni < 4; ni++) {
                const int n0 = wn * 32 + ni * 8 + g;
                bb[ni][0] = f2tf(Bs[s][n0][k0 + tg]);
                bb[ni][1] = f2tf(Bs[s][n0][k0 + tg + 4]);
            }
            #pragma unroll
            for (int mi = 0; mi < 2; mi++)
                #pragma unroll
                for (int ni = 0; ni < 4; ni++)
                    mma_tf32(acc[mi][ni], a[mi][0], a[mi][1], a[mi][2], a[mi][3],
                             bb[ni][0], bb[ni][1]);
        }
        __syncthreads();
    }

    #pragma unroll
    for (int mi = 0; mi < 2; mi++) {
        const int r0 = mtile * 64 + wm * 32 + mi * 16;
        #pragma unroll
        for (int ni = 0; ni < 4; ni++) {
            const int o0 = otile * 64 + wn * 32 + ni * 8 + tg * 2;
            const float b0 = bias[o0], b1 = bias[o0 + 1];
            float2 v0 = { acc[mi][ni][0] + b0, acc[mi][ni][1] + b1 };
            float2 v1 = { acc[mi][ni][2] + b0, acc[mi][ni][3] + b1 };
            *(float2*)&g_gate[gate][l][r0 + g][o0]     = v0;
            *(float2*)&g_gate[gate][l][r0 + g + 8][o0] = v1;
        }
    }
}

// ---------------------------------------------------------------------------
// h_new = sigmoid(alpha) * tanh(phi) + sigmoid(beta) * h    -> d_out[0:H_SIZE]
// float4 vectorized: 65536 float4 elements.
// ---------------------------------------------------------------------------
__global__ __launch_bounds__(256)
void hnew_kernel(const float* __restrict__ h, float* __restrict__ out)
{
    const int idx = blockIdx.x * blockDim.x + threadIdx.x;   // float4 index
    if (idx >= H_SIZE4) return;
    const float4* g = (const float4*)&g_gate[0][0][0][0];
    float4 phi   = g[idx];
    float4 alpha = g[H_SIZE4 + idx];
    float4 beta  = g[2 * H_SIZE4 + idx];
    float4 hv    = ((const float4*)h)[idx];
    float4 o;
    o.x = sigmoidf_(alpha.x) * tanhf(phi.x) + sigmoidf_(beta.x) * hv.x;
    o.y = sigmoidf_(alpha.y) * tanhf(phi.y) + sigmoidf_(beta.y) * hv.y;
    o.z = sigmoidf_(alpha.z) * tanhf(phi.z) + sigmoidf_(beta.z) * hv.z;
    o.w = sigmoidf_(alpha.w) * tanhf(phi.w) + sigmoidf_(beta.w) * hv.w;
    ((float4*)out)[idx] = o;
}

// ---------------------------------------------------------------------------
// u/v GEMM: same structure.  wv = h_new|x|c.  Block M=64 x N=64.
// grid: (otile=4, mtile=2, z=l*2+which=8) = 64 blocks.
// ---------------------------------------------------------------------------
__global__ __launch_bounds__(128)
void uv_gemm(const float* __restrict__ hn, const float* __restrict__ x,
             const float* __restrict__ c,
             const float* __restrict__ u_w, const float* __restrict__ v_w,
             const float* __restrict__ u_b, const float* __restrict__ v_b)
{
    __shared__ float As[2][64][36];
    __shared__ float Bs[2][64][36];

    const int zz = blockIdx.z;
    const int l = zz >> 1, which = zz & 1;
    const int mtile = blockIdx.y;
    const int otile = blockIdx.x;
    const int t = threadIdx.x;
    const int w = t >> 5, lane = t & 31;
    const int wm = w >> 1, wn = w & 1;
    const int g = lane >> 2, tg = lane & 3;

    const float* W    = (which ? v_w : u_w) + (size_t)l * RW * DW;
    const float* bias = (which ? v_b : u_b) + l * RW;

    float acc[2][4][4];
    #pragma unroll
    for (int mi = 0; mi < 2; mi++)
        #pragma unroll
        for (int ni = 0; ni < 4; ni++)
            #pragma unroll
            for (int r = 0; r < 4; r++) acc[mi][ni][r] = 0.0f;

    auto load_chunk = [&](int kt, int s) {
        #pragma unroll
        for (int i = 0; i < 4; i++) {
            const int idx = i * 128 + t;
            const int row = idx >> 3, ch = idx & 7;
            const int k = kt + ch * 4;
            const int b = mtile * 64 + row;
            const float* src;
            if (k < STW)              src = hn + ((size_t)l * BAT + b) * STW + k;
            else if (k < STW + INW)   src = x + (size_t)b * INW + (k - STW);
            else                      src = c + (size_t)b * CTXW + (k - STW - INW);
            cp16(&As[s][row][ch * 4], src);
        }
        #pragma unroll
        for (int i = 0; i < 4; i++) {
            const int idx = i * 128 + t;
            const int row = idx >> 3, ch = idx & 7;
            cp16(&Bs[s][row][ch * 4], W + (size_t)(otile * 64 + row) * DW + kt + ch * 4);
        }
        cp_commit();
    };

    load_chunk(0, 0);
    for (int it = 0; it < NCHUNK; ++it) {
        const int s = it & 1;
        if (it + 1 < NCHUNK) { load_chunk((it + 1) * KC, s ^ 1); cp_wait<1>(); }
        else                 { cp_wait<0>(); }
        __syncthreads();

        #pragma unroll
        for (int ks = 0; ks < 4; ks++) {
            const int k0 = ks * 8;
            unsigned a[2][4];
            #pragma unroll
            for (int mi = 0; mi < 2; mi++) {
                const int r0 = wm * 32 + mi * 16;
                a[mi][0] = f2tf(As[s][r0 + g][k0 + tg]);
                a[mi][1] = f2tf(As[s][r0 + g + 8][k0 + tg]);
                a[mi][2] = f2tf(As[s][r0 + g][k0 + tg + 4]);
                a[mi][3] = f2tf(As[s][r0 + g + 8][k0 + tg + 4]);
            }
            unsigned bb[4][2];
            #pragma unroll
            for (int ni = 0; ni < 4; ni++) {
                const int n0 = wn * 32 + ni * 8 + g;
                bb[ni][0] = f2tf(Bs[s][n0][k0 + tg]);
                bb[ni][1] = f2tf(Bs[s][n0][k0 + tg + 4]);
            }
            #pragma unroll
            for (int mi = 0; mi < 2; mi++)
                #pragma unroll
                for (int ni = 0; ni < 4; ni++)
                    mma_tf32(acc[mi][ni], a[mi][0], a[mi][1], a[mi][2], a[mi][3],
                             bb[ni][0], bb[ni][1]);
        }
        __syncthreads();
    }

    #pragma unroll
    for (int mi = 0; mi < 2; mi++) {
        const int r0 = mtile * 64 + wm * 32 + mi * 16;
        #pragma unroll
        for (int ni = 0; ni < 4; ni++) {
            const int o0 = otile * 64 + wn * 32 + ni * 8 + tg * 2;
            const float b0 = bias[o0], b1 = bias[o0 + 1];
            float2 v0 = { acc[mi][ni][0] + b0, acc[mi][ni][1] + b1 };
            float2 v1 = { acc[mi][ni][2] + b0, acc[mi][ni][3] + b1 };
            *(float2*)&g_uv[which][l][r0 + g][o0]     = v0;
            *(float2*)&g_uv[which][l][r0 + g + 8][o0] = v1;
        }
    }
}

// ---------------------------------------------------------------------------
// M update, fused across all 4 levels so each M element is read exactly once.
// All M traffic is touch-once -> evict-first streaming (__ldcs/__stcs).
// grid: (ichunk=8, b=128), 256 threads, float4 per thread.
// ---------------------------------------------------------------------------
__global__ __launch_bounds__(256)
void m_update(const float* __restrict__ M,
              const float* __restrict__ gamma_logits,
              const float* __restrict__ eta_logits,
              float* __restrict__ out)
{
    __shared__ float sv[4][256];
    __shared__ float su[4][32];
    __shared__ float sg[4], se[4];

    const int b  = blockIdx.y;
    const int ic = blockIdx.x;
    const int t  = threadIdx.x;

    for (int e = t; e < 1024; e += 256) {
        int l = e >> 8, j = e & 255;
        sv[l][j] = g_uv[1][l][b][j];
    }
    if (t < 128) {
        int l = t >> 5, i = t & 31;
        su[l][i] = g_uv[0][l][b][ic * 32 + i];
    }
    if (t < 4) { sg[t] = sigmoidf_(gamma_logits[t]); se[t] = sigmoidf_(eta_logits[t]); }
    __syncthreads();

    float* mout = out + H_SIZE;

    #pragma unroll 1
    for (int it = 0; it < 8; it++) {
        const int p  = it * 256 + t;
        const int i  = p >> 6;
        const int j4 = (p & 63) << 2;
        const int ig = ic * 32 + i;
        const size_t base = ((size_t)b * RW + ig) * CW + j4;

        float4 m[4];
        #pragma unroll
        for (int l = 0; l < 4; l++)
            m[l] = __ldcs((const float4*)(M + (size_t)l * M_LVL_STRIDE + base));

        #pragma unroll
        for (int l = 0; l < 4; l++) {
            const int lu = (l == 0) ? 0 : l - 1;
            const int ld = (l == 3) ? 3 : l + 1;
            const float g = sg[l], e = se[l];
            const float uval = su[l][i];
            const float4 v = *(const float4*)&sv[l][j4];
            float4 o;
            o.x = (1.0f - g) * m[l].x + 0.5f * g * (m[lu].x + m[ld].x) + e * uval * v.x;
            o.y = (1.0f - g) * m[l].y + 0.5f * g * (m[lu].y + m[ld].y) + e * uval * v.y;
            o.z = (1.0f - g) * m[l].z + 0.5f * g * (m[lu].z + m[ld].z) + e * uval * v.z;
            o.w = (1.0f - g) * m[l].w + 0.5f * g * (m[lu].w + m[ld].w) + e * uval * v.w;
            __stcs((float4*)(mout + (size_t)l * M_LVL_STRIDE + base), o);
        }
    }
}

// ---------------------------------------------------------------------------
extern "C" void kernel_launch(void* const* d_in, const int* in_sizes, int n_in,
                              void* d_out, int out_size)
{
    const float* x       = (const float*)d_in[0];
    const float* c       = (const float*)d_in[1];
    const float* h       = (const float*)d_in[2];
    const float* M       = (const float*)d_in[3];
    const float* phi_w   = (const float*)d_in[4];
    const float* phi_b   = (const float*)d_in[5];
    const float* alpha_w = (const float*)d_in[6];
    const float* alpha_b = (const float*)d_in[7];
    const float* beta_w  = (const float*)d_in[8];
    const float* beta_b  = (const float*)d_in[9];
    const float* u_w     = (const float*)d_in[10];
    const float* u_b     = (const float*)d_in[11];
    const float* v_w     = (const float*)d_in[12];
    const float* v_b     = (const float*)d_in[13];
    const float* gamma_l = (const float*)d_in[14];
    const float* eta_l   = (const float*)d_in[15];

    float* out = (float*)d_out;

    // 1. gate GEMMs (tf32 tensor cores, cp.async pipeline) -> g_gate
    gate_gemm<<<dim3(8, 2, 12), 128>>>(x, c, h, phi_w, alpha_w, beta_w,
                                       phi_b, alpha_b, beta_b);
    // 2. h_new -> out[0:H_SIZE]
    hnew_kernel<<<H_SIZE4 / 256, 256>>>(h, out);
    // 3. u/v GEMMs (read h_new from out) -> g_uv
    uv_gemm<<<dim3(4, 2, 8), 128>>>(out, x, c, u_w, v_w, u_b, v_b);
    // 4. fused 4-level M update (streaming) -> out[H_SIZE:]
    m_update<<<dim3(8, 128), 256>>>(M, gamma_l, eta_l, out);
}

// round 10
// speedup vs baseline: 1.1270x; 1.1270x over previous
#include <cuda_runtime.h>
#include <math.h>

#define LVL 4
#define BAT 128
#define INW 512
#define CTXW 512
#define STW 512
#define RW 256
#define CW 256
#define DW 1536
#define KC 32
#define NCHUNK (DW/KC)                /* 48 */
#define H_SIZE (LVL*BAT*STW)          /* 262144 */
#define H_SIZE4 (H_SIZE/4)            /* 65536 */
#define M_LVL_STRIDE (BAT*RW*CW)      /* 8388608 */

// scratch (allocation-free rule: __device__ globals)
__device__ __align__(16) float g_gate[3][LVL][BAT][STW];  // phi/alpha/beta raw (3 MB)
__device__ __align__(16) float g_uv[2][LVL][BAT][RW];     // u,v raw (1 MB)

__device__ __forceinline__ float sigmoidf_(float x) { return 1.0f / (1.0f + __expf(-x)); }

__device__ __forceinline__ unsigned f2tf(float x) {
    unsigned r;
    asm("cvt.rna.tf32.f32 %0, %1;" : "=r"(r) : "f"(x));
    return r;
}

__device__ __forceinline__ void mma_tf32(float* d, unsigned a0, unsigned a1,
                                         unsigned a2, unsigned a3,
                                         unsigned b0, unsigned b1)
{
    asm volatile(
        "mma.sync.aligned.m16n8k8.row.col.f32.tf32.tf32.f32 "
        "{%0,%1,%2,%3}, {%4,%5,%6,%7}, {%8,%9}, {%0,%1,%2,%3};\n"
        : "+f"(d[0]), "+f"(d[1]), "+f"(d[2]), "+f"(d[3])
        : "r"(a0), "r"(a1), "r"(a2), "r"(a3), "r"(b0), "r"(b1));
}

__device__ __forceinline__ void cp16(void* dst, const void* src) {
    unsigned ds = (unsigned)__cvta_generic_to_shared(dst);
    asm volatile("cp.async.ca.shared.global [%0], [%1], 16;" :: "r"(ds), "l"(src));
}
__device__ __forceinline__ void cp_commit() { asm volatile("cp.async.commit_group;"); }
template<int N> __device__ __forceinline__ void cp_wait() {
    asm volatile("cp.async.wait_group %0;" :: "n"(N));
}

// ===========================================================================
// 3-stage pipelined tf32 GEMM core, tile M=64 x N=32, 128 threads
// (2x2 warps, warp tile 32x16).  Stride-36 smem rows -> conflict-free
// fragment reads (bank = (4g+tg) mod 32, bijective over the warp).
//
// Pipeline (single barrier per iteration):
//   prologue: issue stages 0,1 (2 groups)
//   iter it:  wait<1> (drains stage it; wait<0> on the LAST iter — with only
//             one group pending wait<1> would not wait: R6-class bug),
//             __syncthreads (smem visible to all + all reads of slot
//             (it-1)%3 from iter it-1 complete), issue stage it+2 into slot
//             (it-1)%3, compute stage it%3.
//   Overwrite of slot s=it%3 happens at iter it+1's issue, which is after
//   iter it+1's top barrier, which is after every thread's compute(it). Safe.
// ===========================================================================
#define GEMM_PIPE_BODY(LOAD_A_PTR, LOAD_B_PTR)                                 \
    __shared__ float As[3][64][36];                                            \
    __shared__ float Bs[3][32][36];                                            \
    const int t = threadIdx.x;                                                 \
    const int w = t >> 5, lane = t & 31;                                       \
    const int wm = w >> 1, wn = w & 1;                                         \
    const int g = lane >> 2, tg = lane & 3;                                    \
    float acc[2][2][4];                                                        \
    _Pragma("unroll")                                                          \
    for (int mi = 0; mi < 2; mi++)                                             \
        _Pragma("unroll")                                                      \
        for (int ni = 0; ni < 2; ni++)                                         \
            _Pragma("unroll")                                                  \
            for (int r = 0; r < 4; r++) acc[mi][ni][r] = 0.0f;                 \
    auto load_chunk = [&](int kt, int s) {                                     \
        _Pragma("unroll")                                                      \
        for (int i = 0; i < 4; i++) {   /* A: 64x32 = 512 float4 */            \
            const int idx = i * 128 + t;                                       \
            const int row = idx >> 3, ch = idx & 7;                            \
            cp16(&As[s][row][ch * 4], LOAD_A_PTR(row, kt + ch * 4));           \
        }                                                                      \
        _Pragma("unroll")                                                      \
        for (int i = 0; i < 2; i++) {   /* B: 32x32 = 256 float4 */            \
            const int idx = i * 128 + t;                                       \
            const int row = idx >> 3, ch = idx & 7;                            \
            cp16(&Bs[s][row][ch * 4], LOAD_B_PTR(row, kt + ch * 4));           \
        }                                                                      \
        cp_commit();                                                           \
    };                                                                         \
    load_chunk(0, 0);                                                          \
    load_chunk(KC, 1);                                                         \
    for (int it = 0; it < NCHUNK; ++it) {                                      \
        const int s = it % 3;                                                  \
        if (it + 1 < NCHUNK) cp_wait<1>(); else cp_wait<0>();                  \
        __syncthreads();                                                       \
        if (it + 2 < NCHUNK) load_chunk((it + 2) * KC, (it + 2) % 3);          \
        _Pragma("unroll")                                                      \
        for (int ks = 0; ks < 4; ks++) {                                       \
            const int k0 = ks * 8;                                             \
            unsigned a[2][4];                                                  \
            _Pragma("unroll")                                                  \
            for (int mi = 0; mi < 2; mi++) {                                   \
                const int r0 = wm * 32 + mi * 16;                              \
                a[mi][0] = f2tf(As[s][r0 + g][k0 + tg]);                       \
                a[mi][1] = f2tf(As[s][r0 + g + 8][k0 + tg]);                   \
                a[mi][2] = f2tf(As[s][r0 + g][k0 + tg + 4]);                   \
                a[mi][3] = f2tf(As[s][r0 + g + 8][k0 + tg + 4]);               \
            }                                                                  \
            unsigned bb[2][2];                                                 \
            _Pragma("unroll")                                                  \
            for (int ni = 0; ni < 2; ni++) {                                   \
                const int n0 = wn * 16 + ni * 8 + g;                           \
                bb[ni][0] = f2tf(Bs[s][n0][k0 + tg]);                          \
                bb[ni][1] = f2tf(Bs[s][n0][k0 + tg + 4]);                      \
            }                                                                  \
            _Pragma("unroll")                                                  \
            for (int mi = 0; mi < 2; mi++)                                     \
                _Pragma("unroll")                                              \
                for (int ni = 0; ni < 2; ni++)                                 \
                    mma_tf32(acc[mi][ni], a[mi][0], a[mi][1], a[mi][2],        \
                             a[mi][3], bb[ni][0], bb[ni][1]);                  \
        }                                                                      \
    }

// ---------------------------------------------------------------------------
// Gate GEMM: g_gate[gate][l][b][o] = gi[l,b,:] . W[l,o,:] + bias ; gi=x|c|h[l]
// grid: (otile=16, mtile=2, z=l*3+gate=12) = 384 blocks x 128 threads.
// ---------------------------------------------------------------------------
__global__ __launch_bounds__(128)
void gate_gemm(const float* __restrict__ x, const float* __restrict__ c,
               const float* __restrict__ h,
               const float* __restrict__ phi_w, const float* __restrict__ alpha_w,
               const float* __restrict__ beta_w,
               const float* __restrict__ phi_b, const float* __restrict__ alpha_b,
               const float* __restrict__ beta_b)
{
    const int zz = blockIdx.z;
    const int l = zz / 3, gate = zz % 3;
    const int mtile = blockIdx.y;
    const int otile = blockIdx.x;

    const float* W    = (gate == 0 ? phi_w : gate == 1 ? alpha_w : beta_w) + (size_t)l * STW * DW;
    const float* bias = (gate == 0 ? phi_b : gate == 1 ? alpha_b : beta_b) + l * STW;

    #define GA_PTR(row, k)                                                      \
        ((k) < INW ? x + (size_t)(mtile * 64 + (row)) * INW + (k)               \
         : (k) < INW + CTXW ? c + (size_t)(mtile * 64 + (row)) * CTXW + ((k) - INW) \
         : h + ((size_t)l * BAT + mtile * 64 + (row)) * STW + ((k) - INW - CTXW))
    #define GB_PTR(row, k)  (W + (size_t)(otile * 32 + (row)) * DW + (k))

    GEMM_PIPE_BODY(GA_PTR, GB_PTR)

    #undef GA_PTR
    #undef GB_PTR

    #pragma unroll
    for (int mi = 0; mi < 2; mi++) {
        const int r0 = mtile * 64 + wm * 32 + mi * 16;
        #pragma unroll
        for (int ni = 0; ni < 2; ni++) {
            const int o0 = otile * 32 + wn * 16 + ni * 8 + tg * 2;
            const float b0 = bias[o0], b1 = bias[o0 + 1];
            float2 v0 = { acc[mi][ni][0] + b0, acc[mi][ni][1] + b1 };
            float2 v1 = { acc[mi][ni][2] + b0, acc[mi][ni][3] + b1 };
            *(float2*)&g_gate[gate][l][r0 + g][o0]     = v0;
            *(float2*)&g_gate[gate][l][r0 + g + 8][o0] = v1;
        }
    }
}

// ---------------------------------------------------------------------------
// h_new = sigmoid(alpha) * tanh(phi) + sigmoid(beta) * h    -> d_out[0:H_SIZE]
// ---------------------------------------------------------------------------
__global__ __launch_bounds__(256)
void hnew_kernel(const float* __restrict__ h, float* __restrict__ out)
{
    const int idx = blockIdx.x * blockDim.x + threadIdx.x;   // float4 index
    if (idx >= H_SIZE4) return;
    const float4* g = (const float4*)&g_gate[0][0][0][0];
    float4 phi   = g[idx];
    float4 alpha = g[H_SIZE4 + idx];
    float4 beta  = g[2 * H_SIZE4 + idx];
    float4 hv    = ((const float4*)h)[idx];
    float4 o;
    o.x = sigmoidf_(alpha.x) * tanhf(phi.x) + sigmoidf_(beta.x) * hv.x;
    o.y = sigmoidf_(alpha.y) * tanhf(phi.y) + sigmoidf_(beta.y) * hv.y;
    o.z = sigmoidf_(alpha.z) * tanhf(phi.z) + sigmoidf_(beta.z) * hv.z;
    o.w = sigmoidf_(alpha.w) * tanhf(phi.w) + sigmoidf_(beta.w) * hv.w;
    ((float4*)out)[idx] = o;
}

// ---------------------------------------------------------------------------
// u/v GEMM: wv = h_new|x|c.  grid: (otile=8, mtile=2, z=l*2+which=8) = 128.
// ---------------------------------------------------------------------------
__global__ __launch_bounds__(128)
void uv_gemm(const float* __restrict__ hn, const float* __restrict__ x,
             const float* __restrict__ c,
             const float* __restrict__ u_w, const float* __restrict__ v_w,
             const float* __restrict__ u_b, const float* __restrict__ v_b)
{
    const int zz = blockIdx.z;
    const int l = zz >> 1, which = zz & 1;
    const int mtile = blockIdx.y;
    const int otile = blockIdx.x;

    const float* W    = (which ? v_w : u_w) + (size_t)l * RW * DW;
    const float* bias = (which ? v_b : u_b) + l * RW;

    #define UA_PTR(row, k)                                                      \
        ((k) < STW ? hn + ((size_t)l * BAT + mtile * 64 + (row)) * STW + (k)    \
         : (k) < STW + INW ? x + (size_t)(mtile * 64 + (row)) * INW + ((k) - STW) \
         : c + (size_t)(mtile * 64 + (row)) * CTXW + ((k) - STW - INW))
    #define UB_PTR(row, k)  (W + (size_t)(otile * 32 + (row)) * DW + (k))

    GEMM_PIPE_BODY(UA_PTR, UB_PTR)

    #undef UA_PTR
    #undef UB_PTR

    #pragma unroll
    for (int mi = 0; mi < 2; mi++) {
        const int r0 = mtile * 64 + wm * 32 + mi * 16;
        #pragma unroll
        for (int ni = 0; ni < 2; ni++) {
            const int o0 = otile * 32 + wn * 16 + ni * 8 + tg * 2;
            const float b0 = bias[o0], b1 = bias[o0 + 1];
            float2 v0 = { acc[mi][ni][0] + b0, acc[mi][ni][1] + b1 };
            float2 v1 = { acc[mi][ni][2] + b0, acc[mi][ni][3] + b1 };
            *(float2*)&g_uv[which][l][r0 + g][o0]     = v0;
            *(float2*)&g_uv[which][l][r0 + g + 8][o0] = v1;
        }
    }
}

// ---------------------------------------------------------------------------
// M update, fused across all 4 levels so each M element is read exactly once.
// Touch-once traffic -> evict-first streaming (__ldcs/__stcs).  2x manual
// unroll -> 8 ldcs in flight per thread (MLP doubled vs R9).
// grid: (ichunk=8, b=128), 256 threads.
// ---------------------------------------------------------------------------
__global__ __launch_bounds__(256)
void m_update(const float* __restrict__ M,
              const float* __restrict__ gamma_logits,
              const float* __restrict__ eta_logits,
              float* __restrict__ out)
{
    __shared__ float sv[4][256];
    __shared__ float su[4][32];
    __shared__ float sg[4], se[4];

    const int b  = blockIdx.y;
    const int ic = blockIdx.x;
    const int t  = threadIdx.x;

    for (int e = t; e < 1024; e += 256) {
        int l = e >> 8, j = e & 255;
        sv[l][j] = g_uv[1][l][b][j];
    }
    if (t < 128) {
        int l = t >> 5, i = t & 31;
        su[l][i] = g_uv[0][l][b][ic * 32 + i];
    }
    if (t < 4) { sg[t] = sigmoidf_(gamma_logits[t]); se[t] = sigmoidf_(eta_logits[t]); }
    __syncthreads();

    float* mout = out + H_SIZE;

    #pragma unroll 1
    for (int it = 0; it < 8; it += 2) {
        const int p0 = it * 256 + t;
        const int p1 = p0 + 256;
        const int i0 = p0 >> 6,          i1 = p1 >> 6;
        const int j40 = (p0 & 63) << 2,  j41 = (p1 & 63) << 2;
        const size_t base0 = ((size_t)b * RW + ic * 32 + i0) * CW + j40;
        const size_t base1 = ((size_t)b * RW + ic * 32 + i1) * CW + j41;

        float4 m0[4], m1[4];
        #pragma unroll
        for (int l = 0; l < 4; l++)
            m0[l] = __ldcs((const float4*)(M + (size_t)l * M_LVL_STRIDE + base0));
        #pragma unroll
        for (int l = 0; l < 4; l++)
            m1[l] = __ldcs((const float4*)(M + (size_t)l * M_LVL_STRIDE + base1));

        #pragma unroll
        for (int l = 0; l < 4; l++) {
            const int lu = (l == 0) ? 0 : l - 1;
            const int ld = (l == 3) ? 3 : l + 1;
            const float gg = sg[l], e = se[l];
            const float u0 = e * su[l][i0];
            const float4 v0 = *(const float4*)&sv[l][j40];
            float4 o;
            o.x = (1.0f - gg) * m0[l].x + 0.5f * gg * (m0[lu].x + m0[ld].x) + u0 * v0.x;
            o.y = (1.0f - gg) * m0[l].y + 0.5f * gg * (m0[lu].y + m0[ld].y) + u0 * v0.y;
            o.z = (1.0f - gg) * m0[l].z + 0.5f * gg * (m0[lu].z + m0[ld].z) + u0 * v0.z;
            o.w = (1.0f - gg) * m0[l].w + 0.5f * gg * (m0[lu].w + m0[ld].w) + u0 * v0.w;
            __stcs((float4*)(mout + (size_t)l * M_LVL_STRIDE + base0), o);
        }
        #pragma unroll
        for (int l = 0; l < 4; l++) {
            const int lu = (l == 0) ? 0 : l - 1;
            const int ld = (l == 3) ? 3 : l + 1;
            const float gg = sg[l], e = se[l];
            const float u1 = e * su[l][i1];
            const float4 v1 = *(const float4*)&sv[l][j41];
            float4 o;
            o.x = (1.0f - gg) * m1[l].x + 0.5f * gg * (m1[lu].x + m1[ld].x) + u1 * v1.x;
            o.y = (1.0f - gg) * m1[l].y + 0.5f * gg * (m1[lu].y + m1[ld].y) + u1 * v1.y;
            o.z = (1.0f - gg) * m1[l].z + 0.5f * gg * (m1[lu].z + m1[ld].z) + u1 * v1.z;
            o.w = (1.0f - gg) * m1[l].w + 0.5f * gg * (m1[lu].w + m1[ld].w) + u1 * v1.w;
            __stcs((float4*)(mout + (size_t)l * M_LVL_STRIDE + base1), o);
        }
    }
}

// ---------------------------------------------------------------------------
extern "C" void kernel_launch(void* const* d_in, const int* in_sizes, int n_in,
                              void* d_out, int out_size)
{
    const float* x       = (const float*)d_in[0];
    const float* c       = (const float*)d_in[1];
    const float* h       = (const float*)d_in[2];
    const float* M       = (const float*)d_in[3];
    const float* phi_w   = (const float*)d_in[4];
    const float* phi_b   = (const float*)d_in[5];
    const float* alpha_w = (const float*)d_in[6];
    const float* alpha_b = (const float*)d_in[7];
    const float* beta_w  = (const float*)d_in[8];
    const float* beta_b  = (const float*)d_in[9];
    const float* u_w     = (const float*)d_in[10];
    const float* u_b     = (const float*)d_in[11];
    const float* v_w     = (const float*)d_in[12];
    const float* v_b     = (const float*)d_in[13];
    const float* gamma_l = (const float*)d_in[14];
    const float* eta_l   = (const float*)d_in[15];

    float* out = (float*)d_out;

    // 1. gate GEMMs (tf32, 3-stage cp.async pipeline) -> g_gate
    gate_gemm<<<dim3(16, 2, 12), 128>>>(x, c, h, phi_w, alpha_w, beta_w,
                                        phi_b, alpha_b, beta_b);
    // 2. h_new -> out[0:H_SIZE]
    hnew_kernel<<<H_SIZE4 / 256, 256>>>(h, out);
    // 3. u/v GEMMs (read h_new from out) -> g_uv
    uv_gemm<<<dim3(8, 2, 8), 128>>>(out, x, c, u_w, v_w, u_b, v_b);
    // 4. fused 4-level M update (streaming, 2x unrolled) -> out[H_SIZE:]
    m_update<<<dim3(8, 128), 256>>>(M, gamma_l, eta_l, out);
}

// round 11
// speedup vs baseline: 1.1827x; 1.0494x over previous
#include <cuda_runtime.h>
#include <math.h>

#define LVL 4
#define BAT 128
#define INW 512
#define CTXW 512
#define STW 512
#define RW 256
#define CW 256
#define DW 1536
#define KC 32
#define KHALF 768                     /* K per split-K block */
#define NCH (KHALF/KC)                /* 24 chunks per half */
#define H_SIZE (LVL*BAT*STW)          /* 262144 */
#define H_SIZE4 (H_SIZE/4)            /* 65536 */
#define M_LVL_STRIDE (BAT*RW*CW)      /* 8388608 */

// scratch (allocation-free rule: __device__ globals)
__device__ __align__(16) float g_gate_p[2][3][LVL][BAT][STW]; // split-K gate partials (6 MB)
__device__ __align__(16) float g_uv_p[2][2][LVL][BAT][RW];    // split-K u/v partials (2 MB)

__device__ __forceinline__ float sigmoidf_(float x) { return 1.0f / (1.0f + __expf(-x)); }

__device__ __forceinline__ unsigned f2tf(float x) {
    unsigned r;
    asm("cvt.rna.tf32.f32 %0, %1;" : "=r"(r) : "f"(x));
    return r;
}

__device__ __forceinline__ void mma_tf32(float* d, unsigned a0, unsigned a1,
                                         unsigned a2, unsigned a3,
                                         unsigned b0, unsigned b1)
{
    asm volatile(
        "mma.sync.aligned.m16n8k8.row.col.f32.tf32.tf32.f32 "
        "{%0,%1,%2,%3}, {%4,%5,%6,%7}, {%8,%9}, {%0,%1,%2,%3};\n"
        : "+f"(d[0]), "+f"(d[1]), "+f"(d[2]), "+f"(d[3])
        : "r"(a0), "r"(a1), "r"(a2), "r"(a3), "r"(b0), "r"(b1));
}

__device__ __forceinline__ void cp16(void* dst, const void* src) {
    unsigned ds = (unsigned)__cvta_generic_to_shared(dst);
    asm volatile("cp.async.ca.shared.global [%0], [%1], 16;" :: "r"(ds), "l"(src));
}
__device__ __forceinline__ void cp_commit() { asm volatile("cp.async.commit_group;"); }
template<int N> __device__ __forceinline__ void cp_wait() {
    asm volatile("cp.async.wait_group %0;" :: "n"(N));
}

// ===========================================================================
// 3-stage pipelined tf32 GEMM core over K range [KBASE, KBASE+KHALF).
// Tile M=64 x N=32, 128 threads (2x2 warps, warp tile 32x16).
// Stride-36 smem rows -> conflict-free fragment reads.
// Pipeline: prologue issues stages 0,1; per iter: wait<1> (wait<0> on last
// iter — wait<1> with 1 pending group would not wait: R6-class bug),
// barrier, issue stage it+2 into slot (it+2)%3 (its prior contents were
// last read before this barrier), compute stage it%3.  R10-proven.
// ===========================================================================
#define GEMM_PIPE_BODY(LOAD_A_PTR, LOAD_B_PTR, KBASE)                          \
    __shared__ float As[3][64][36];                                            \
    __shared__ float Bs[3][32][36];                                            \
    const int t = threadIdx.x;                                                 \
    const int w = t >> 5, lane = t & 31;                                       \
    const int wm = w >> 1, wn = w & 1;                                         \
    const int g = lane >> 2, tg = lane & 3;                                    \
    float acc[2][2][4];                                                        \
    _Pragma("unroll")                                                          \
    for (int mi = 0; mi < 2; mi++)                                             \
        _Pragma("unroll")                                                      \
        for (int ni = 0; ni < 2; ni++)                                         \
            _Pragma("unroll")                                                  \
            for (int r = 0; r < 4; r++) acc[mi][ni][r] = 0.0f;                 \
    auto load_chunk = [&](int kt, int s) {                                     \
        _Pragma("unroll")                                                      \
        for (int i = 0; i < 4; i++) {   /* A: 64x32 = 512 float4 */            \
            const int idx = i * 128 + t;                                       \
            const int row = idx >> 3, ch = idx & 7;                            \
            cp16(&As[s][row][ch * 4], LOAD_A_PTR(row, kt + ch * 4));           \
        }                                                                      \
        _Pragma("unroll")                                                      \
        for (int i = 0; i < 2; i++) {   /* B: 32x32 = 256 float4 */            \
            const int idx = i * 128 + t;                                       \
            const int row = idx >> 3, ch = idx & 7;                            \
            cp16(&Bs[s][row][ch * 4], LOAD_B_PTR(row, kt + ch * 4));           \
        }                                                                      \
        cp_commit();                                                           \
    };                                                                         \
    load_chunk(KBASE, 0);                                                      \
    load_chunk(KBASE + KC, 1);                                                 \
    for (int it = 0; it < NCH; ++it) {                                         \
        const int s = it % 3;                                                  \
        if (it + 1 < NCH) cp_wait<1>(); else cp_wait<0>();                     \
        __syncthreads();                                                       \
        if (it + 2 < NCH) load_chunk(KBASE + (it + 2) * KC, (it + 2) % 3);     \
        _Pragma("unroll")                                                      \
        for (int ks = 0; ks < 4; ks++) {                                       \
            const int k0 = ks * 8;                                             \
            unsigned a[2][4];                                                  \
            _Pragma("unroll")                                                  \
            for (int mi = 0; mi < 2; mi++) {                                   \
                const int r0 = wm * 32 + mi * 16;                              \
                a[mi][0] = f2tf(As[s][r0 + g][k0 + tg]);                       \
                a[mi][1] = f2tf(As[s][r0 + g + 8][k0 + tg]);                   \
                a[mi][2] = f2tf(As[s][r0 + g][k0 + tg + 4]);                   \
                a[mi][3] = f2tf(As[s][r0 + g + 8][k0 + tg + 4]);               \
            }                                                                  \
            unsigned bb[2][2];                                                 \
            _Pragma("unroll")                                                  \
            for (int ni = 0; ni < 2; ni++) {                                   \
                const int n0 = wn * 16 + ni * 8 + g;                           \
                bb[ni][0] = f2tf(Bs[s][n0][k0 + tg]);                          \
                bb[ni][1] = f2tf(Bs[s][n0][k0 + tg + 4]);                      \
            }                                                                  \
            _Pragma("unroll")                                                  \
            for (int mi = 0; mi < 2; mi++)                                     \
                _Pragma("unroll")                                              \
                for (int ni = 0; ni < 2; ni++)                                 \
                    mma_tf32(acc[mi][ni], a[mi][0], a[mi][1], a[mi][2],        \
                             a[mi][3], bb[ni][0], bb[ni][1]);                  \
        }                                                                      \
    }

// ---------------------------------------------------------------------------
// Gate GEMM, split-K x2: g_gate_p[kh][gate][l][b][o] = partial dot (no bias).
// gi = x|c|h[l].  grid: (otile=16, y=mtile*2+kh=4, z=l*3+gate=12) = 768 blocks.
// ---------------------------------------------------------------------------
__global__ __launch_bounds__(128)
void gate_gemm(const float* __restrict__ x, const float* __restrict__ c,
               const float* __restrict__ h,
               const float* __restrict__ phi_w, const float* __restrict__ alpha_w,
               const float* __restrict__ beta_w)
{
    const int zz = blockIdx.z;
    const int l = zz / 3, gate = zz % 3;
    const int mtile = blockIdx.y >> 1;
    const int kh    = blockIdx.y & 1;
    const int otile = blockIdx.x;
    const int kbase = kh * KHALF;

    const float* W = (gate == 0 ? phi_w : gate == 1 ? alpha_w : beta_w) + (size_t)l * STW * DW;

    #define GA_PTR(row, k)                                                      \
        ((k) < INW ? x + (size_t)(mtile * 64 + (row)) * INW + (k)               \
         : (k) < INW + CTXW ? c + (size_t)(mtile * 64 + (row)) * CTXW + ((k) - INW) \
         : h + ((size_t)l * BAT + mtile * 64 + (row)) * STW + ((k) - INW - CTXW))
    #define GB_PTR(row, k)  (W + (size_t)(otile * 32 + (row)) * DW + (k))

    GEMM_PIPE_BODY(GA_PTR, GB_PTR, kbase)

    #undef GA_PTR
    #undef GB_PTR

    #pragma unroll
    for (int mi = 0; mi < 2; mi++) {
        const int r0 = mtile * 64 + wm * 32 + mi * 16;
        #pragma unroll
        for (int ni = 0; ni < 2; ni++) {
            const int o0 = otile * 32 + wn * 16 + ni * 8 + tg * 2;
            float2 v0 = { acc[mi][ni][0], acc[mi][ni][1] };
            float2 v1 = { acc[mi][ni][2], acc[mi][ni][3] };
            *(float2*)&g_gate_p[kh][gate][l][r0 + g][o0]     = v0;
            *(float2*)&g_gate_p[kh][gate][l][r0 + g + 8][o0] = v1;
        }
    }
}

// ---------------------------------------------------------------------------
// h_new = sigmoid(alpha)*tanh(phi) + sigmoid(beta)*h  -> d_out[0:H_SIZE]
// Sums the two split-K partials and adds biases.  float4 vectorized.
// ---------------------------------------------------------------------------
__global__ __launch_bounds__(256)
void hnew_kernel(const float* __restrict__ h,
                 const float* __restrict__ phi_b, const float* __restrict__ alpha_b,
                 const float* __restrict__ beta_b,
                 float* __restrict__ out)
{
    const int idx = blockIdx.x * blockDim.x + threadIdx.x;   // float4 index
    if (idx >= H_SIZE4) return;
    const float4* g0 = (const float4*)&g_gate_p[0][0][0][0][0];
    const float4* g1 = (const float4*)&g_gate_p[1][0][0][0][0];

    const int base = idx * 4;
    const int l = base >> 16;          // BAT*STW = 65536
    const int o = base & (STW - 1);
    const float4 pb = *(const float4*)(phi_b   + l * STW + o);
    const float4 ab = *(const float4*)(alpha_b + l * STW + o);
    const float4 bbv = *(const float4*)(beta_b + l * STW + o);

    float4 p0 = g0[idx],               p1 = g1[idx];
    float4 a0 = g0[H_SIZE4 + idx],     a1 = g1[H_SIZE4 + idx];
    float4 b0 = g0[2 * H_SIZE4 + idx], b1 = g1[2 * H_SIZE4 + idx];
    float4 hv = ((const float4*)h)[idx];

    float4 o4;
    o4.x = sigmoidf_(a0.x + a1.x + ab.x) * tanhf(p0.x + p1.x + pb.x) + sigmoidf_(b0.x + b1.x + bbv.x) * hv.x;
    o4.y = sigmoidf_(a0.y + a1.y + ab.y) * tanhf(p0.y + p1.y + pb.y) + sigmoidf_(b0.y + b1.y + bbv.y) * hv.y;
    o4.z = sigmoidf_(a0.z + a1.z + ab.z) * tanhf(p0.z + p1.z + pb.z) + sigmoidf_(b0.z + b1.z + bbv.z) * hv.z;
    o4.w = sigmoidf_(a0.w + a1.w + ab.w) * tanhf(p0.w + p1.w + pb.w) + sigmoidf_(b0.w + b1.w + bbv.w) * hv.w;
    ((float4*)out)[idx] = o4;
}

// ---------------------------------------------------------------------------
// u/v GEMM, split-K x2: g_uv_p[kh][which][l][b][r] = partial dot (no bias).
// wv = h_new|x|c.  grid: (otile=8, y=mtile*2+kh=4, z=l*2+which=8) = 256.
// ---------------------------------------------------------------------------
__global__ __launch_bounds__(128)
void uv_gemm(const float* __restrict__ hn, const float* __restrict__ x,
             const float* __restrict__ c,
             const float* __restrict__ u_w, const float* __restrict__ v_w)
{
    const int zz = blockIdx.z;
    const int l = zz >> 1, which = zz & 1;
    const int mtile = blockIdx.y >> 1;
    const int kh    = blockIdx.y & 1;
    const int otile = blockIdx.x;
    const int kbase = kh * KHALF;

    const float* W = (which ? v_w : u_w) + (size_t)l * RW * DW;

    #define UA_PTR(row, k)                                                      \
        ((k) < STW ? hn + ((size_t)l * BAT + mtile * 64 + (row)) * STW + (k)    \
         : (k) < STW + INW ? x + (size_t)(mtile * 64 + (row)) * INW + ((k) - STW) \
         : c + (size_t)(mtile * 64 + (row)) * CTXW + ((k) - STW - INW))
    #define UB_PTR(row, k)  (W + (size_t)(otile * 32 + (row)) * DW + (k))

    GEMM_PIPE_BODY(UA_PTR, UB_PTR, kbase)

    #undef UA_PTR
    #undef UB_PTR

    #pragma unroll
    for (int mi = 0; mi < 2; mi++) {
        const int r0 = mtile * 64 + wm * 32 + mi * 16;
        #pragma unroll
        for (int ni = 0; ni < 2; ni++) {
            const int o0 = otile * 32 + wn * 16 + ni * 8 + tg * 2;
            float2 v0 = { acc[mi][ni][0], acc[mi][ni][1] };
            float2 v1 = { acc[mi][ni][2], acc[mi][ni][3] };
            *(float2*)&g_uv_p[kh][which][l][r0 + g][o0]     = v0;
            *(float2*)&g_uv_p[kh][which][l][r0 + g + 8][o0] = v1;
        }
    }
}

// ---------------------------------------------------------------------------
// M update, fused across all 4 levels (each M element read exactly once).
// Sums u/v split-K partials + biases at staging.  Touch-once traffic ->
// evict-first streaming (__ldcs/__stcs).  R9 register shape (no unroll).
// grid: (ichunk=16, b=128) = 2048 blocks, 256 threads, 4 iters/thread.
// ---------------------------------------------------------------------------
__global__ __launch_bounds__(256)
void m_update(const float* __restrict__ M,
              const float* __restrict__ gamma_logits,
              const float* __restrict__ eta_logits,
              const float* __restrict__ u_b, const float* __restrict__ v_b,
              float* __restrict__ out)
{
    __shared__ float sv[4][256];
    __shared__ float su[4][16];
    __shared__ float sg[4], se[4];

    const int b  = blockIdx.y;
    const int ic = blockIdx.x;     // 0..15: 16-row chunk of i
    const int t  = threadIdx.x;

    for (int e = t; e < 1024; e += 256) {
        int l = e >> 8, j = e & 255;
        sv[l][j] = g_uv_p[0][1][l][b][j] + g_uv_p[1][1][l][b][j] + v_b[l * RW + j];
    }
    if (t < 64) {
        int l = t >> 4, i = t & 15;
        int r = ic * 16 + i;
        su[l][i] = g_uv_p[0][0][l][b][r] + g_uv_p[1][0][l][b][r] + u_b[l * RW + r];
    }
    if (t < 4) { sg[t] = sigmoidf_(gamma_logits[t]); se[t] = sigmoidf_(eta_logits[t]); }
    __syncthreads();

    float* mout = out + H_SIZE;

    #pragma unroll 1
    for (int it = 0; it < 4; it++) {
        const int p  = it * 256 + t;
        const int i  = p >> 6;              // 0..15
        const int j4 = (p & 63) << 2;       // 0..252
        const size_t base = ((size_t)b * RW + ic * 16 + i) * CW + j4;

        float4 m[4];
        #pragma unroll
        for (int l = 0; l < 4; l++)
            m[l] = __ldcs((const float4*)(M + (size_t)l * M_LVL_STRIDE + base));

        #pragma unroll
        for (int l = 0; l < 4; l++) {
            const int lu = (l == 0) ? 0 : l - 1;
            const int ld = (l == 3) ? 3 : l + 1;
            const float gg = sg[l];
            const float ue = se[l] * su[l][i];
            const float4 v = *(const float4*)&sv[l][j4];
            float4 o;
            o.x = (1.0f - gg) * m[l].x + 0.5f * gg * (m[lu].x + m[ld].x) + ue * v.x;
            o.y = (1.0f - gg) * m[l].y + 0.5f * gg * (m[lu].y + m[ld].y) + ue * v.y;
            o.z = (1.0f - gg) * m[l].z + 0.5f * gg * (m[lu].z + m[ld].z) + ue * v.z;
            o.w = (1.0f - gg) * m[l].w + 0.5f * gg * (m[lu].w + m[ld].w) + ue * v.w;
            __stcs((float4*)(mout + (size_t)l * M_LVL_STRIDE + base), o);
        }
    }
}

// ---------------------------------------------------------------------------
extern "C" void kernel_launch(void* const* d_in, const int* in_sizes, int n_in,
                              void* d_out, int out_size)
{
    const float* x       = (const float*)d_in[0];
    const float* c       = (const float*)d_in[1];
    const float* h       = (const float*)d_in[2];
    const float* M       = (const float*)d_in[3];
    const float* phi_w   = (const float*)d_in[4];
    const float* phi_b   = (const float*)d_in[5];
    const float* alpha_w = (const float*)d_in[6];
    const float* alpha_b = (const float*)d_in[7];
    const float* beta_w  = (const float*)d_in[8];
    const float* beta_b  = (const float*)d_in[9];
    const float* u_w     = (const float*)d_in[10];
    const float* u_b     = (const float*)d_in[11];
    const float* v_w     = (const float*)d_in[12];
    const float* v_b     = (const float*)d_in[13];
    const float* gamma_l = (const float*)d_in[14];
    const float* eta_l   = (const float*)d_in[15];

    float* out = (float*)d_out;

    // 1. gate GEMMs, split-K x2 (768 blocks, ~5/SM) -> g_gate_p
    gate_gemm<<<dim3(16, 4, 12), 128>>>(x, c, h, phi_w, alpha_w, beta_w);
    // 2. h_new (sums partials + biases) -> out[0:H_SIZE]
    hnew_kernel<<<H_SIZE4 / 256, 256>>>(h, phi_b, alpha_b, beta_b, out);
    // 3. u/v GEMMs, split-K x2 (256 blocks) -> g_uv_p
    uv_gemm<<<dim3(8, 4, 8), 128>>>(out, x, c, u_w, v_w);
    // 4. fused 4-level M update (sums u/v partials + biases) -> out[H_SIZE:]
    m_update<<<dim3(16, 128), 256>>>(M, gamma_l, eta_l, u_b, v_b, out);
}